// round 3
// baseline (speedup 1.0000x reference)
#include <cuda_runtime.h>
#include <math.h>
#include <stdint.h>

#define NN    50000
#define NE    800000
#define FIN   128
#define HID   32
#define HEADS 4
#define D1    128      // HEADS*HID
#define NCLS  16
#define MLPH  128
#define KMAX  16
#define NEG_SLOPE 0.2f

// ---------------- scratch (static device memory; no runtime allocs) ----------------
__device__ int   g_src[NE], g_dst[NE], g_elist[NE];
__device__ int   g_counts[NN], g_offs[NN], g_cursor[NN];
__device__ float g_xl1[(size_t)NN * D1], g_xr1[(size_t)NN * D1];
__device__ float g_scores1[(size_t)NE * HEADS];
__device__ float g_alpha1[(size_t)NE * HEADS], g_alphan1[(size_t)NE * HEADS];
__device__ float g_h1[(size_t)NN * D1], g_noise1[(size_t)NN * D1];
__device__ float g_mlph[(size_t)NN * MLPH];
__device__ float g_n1[NN * NCLS];
__device__ float g_xl2[NN * NCLS], g_xr2[NN * NCLS];
__device__ float g_scores2[NE], g_alpha2[NE], g_alphan2[NE];
__device__ float g_out2[NN * NCLS], g_noise2[NN * NCLS];

// ---------------- small utility kernels ----------------
__global__ void init_csr_kernel() {
    int i = blockIdx.x * blockDim.x + threadIdx.x;
    if (i < NN) { g_counts[i] = 0; g_cursor[i] = 0; }
}

// edge_index is int32 (JAX x64 is disabled; jnp.int64 silently becomes int32)
__global__ void convert_edges_kernel(const int* __restrict__ ei) {
    int e = blockIdx.x * blockDim.x + threadIdx.x;
    if (e < NE) {
        int s = ei[e];
        int d = ei[NE + e];
        s = min(max(s, 0), NN - 1);   // defensive clamp (branch-free)
        d = min(max(d, 0), NN - 1);
        g_src[e] = s;
        g_dst[e] = d;
    }
}

__global__ void count_kernel() {
    int e = blockIdx.x * blockDim.x + threadIdx.x;
    if (e < NE) atomicAdd(&g_counts[g_dst[e]], 1);
}

// single-block exclusive scan of counts -> offs
__global__ void scan_kernel() {
    __shared__ int sh[1024];
    int t = threadIdx.x;
    const int n = NN;
    int per = (n + 1023) / 1024;
    int start = t * per;
    int end = min(start + per, n);
    int sum = 0;
    for (int i = start; i < end; i++) sum += g_counts[i];
    sh[t] = sum;
    __syncthreads();
    for (int off = 1; off < 1024; off <<= 1) {
        int v = (t >= off) ? sh[t - off] : 0;
        __syncthreads();
        sh[t] += v;
        __syncthreads();
    }
    int base = (t == 0) ? 0 : sh[t - 1];
    int run = base;
    for (int i = start; i < end; i++) { g_offs[i] = run; run += g_counts[i]; }
}

__global__ void scatter_kernel() {
    int e = blockIdx.x * blockDim.x + threadIdx.x;
    if (e < NE) {
        int d = g_dst[e];
        int pos = g_offs[d] + atomicAdd(&g_cursor[d], 1);
        g_elist[pos] = e;
    }
}

// ---------------- SGEMM: C[M,128] = A[M,128] @ B[128,128] (+bias, act) -------------
// tag: 0 -> C=g_xl1 (A=param), 1 -> C=g_xr1 (A=param), 2 -> C=g_mlph (A=g_noise1)
__global__ void sgemm128_kernel(int tag, const float* __restrict__ Aparam,
                                const float* __restrict__ B,
                                const float* __restrict__ bias, int act) {
    const int M = NN, N = 128, K = 128;
    const int BM = 64, BK = 16, TM = 4, TN = 4;
    const float* A = (tag == 2) ? (const float*)g_noise1 : Aparam;
    float* C = (tag == 0) ? g_xl1 : (tag == 1) ? g_xr1 : g_mlph;
    __shared__ float As[BK][BM];
    __shared__ float Bs[BK][64];
    int row0 = blockIdx.x * BM;
    int col0 = blockIdx.y * 64;
    int tid = threadIdx.x;              // 256 threads
    int tx = tid % 16, ty = tid / 16;
    int lr = tid / 16, lc = tid % 16;
    int br = tid / 64, bc = tid % 64;
    float acc[TM][TN] = {};
    for (int k0 = 0; k0 < K; k0 += BK) {
#pragma unroll
        for (int i = 0; i < 4; i++) {
            int r = row0 + lr + 16 * i;
            float v = 0.f;
            if (r < M) v = A[(size_t)r * K + k0 + lc];
            As[lc][lr + 16 * i] = v;
        }
#pragma unroll
        for (int i = 0; i < 4; i++) {
            int kr = k0 + br + 4 * i;
            Bs[br + 4 * i][bc] = B[(size_t)kr * N + col0 + bc];
        }
        __syncthreads();
#pragma unroll
        for (int kk = 0; kk < BK; kk++) {
            float a[TM], b[TN];
#pragma unroll
            for (int i = 0; i < TM; i++) a[i] = As[kk][ty * TM + i];
#pragma unroll
            for (int j = 0; j < TN; j++) b[j] = Bs[kk][tx * TN + j];
#pragma unroll
            for (int i = 0; i < TM; i++)
#pragma unroll
                for (int j = 0; j < TN; j++) acc[i][j] += a[i] * b[j];
        }
        __syncthreads();
    }
#pragma unroll
    for (int i = 0; i < TM; i++) {
        int r = row0 + ty * TM + i;
        if (r >= M) continue;
#pragma unroll
        for (int j = 0; j < TN; j++) {
            int c = col0 + tx * TN + j;
            float v = acc[i][j];
            if (bias) v += bias[c];
            if (act == 1) v = (v > 0.f) ? v : expm1f(v);
            C[(size_t)r * N + c] = v;
        }
    }
}

// N=16 GEMM: C[M,16] = A[M,128] @ B[128,16]
// tag: 0 -> A=g_mlph,C=g_n1 ; 1 -> A=g_h1,C=g_xl2 ; 2 -> A=g_h1,C=g_xr2
__global__ void sgemm_n16_kernel(int tag, const float* __restrict__ B,
                                 const float* __restrict__ bias) {
    const int M = NN, K = 128;
    const float* A = (tag == 0) ? (const float*)g_mlph : (const float*)g_h1;
    float* C = (tag == 0) ? g_n1 : (tag == 1) ? g_xl2 : g_xr2;
    __shared__ float Bs[K * 16];
    __shared__ float As[16][K];
    int tid = threadIdx.x;              // 256
    int tx = tid % 16, ty = tid / 16;
    for (int i = tid; i < K * 16; i += 256) Bs[i] = B[i];
    int r = blockIdx.x * 16 + ty;
#pragma unroll
    for (int i = 0; i < 8; i++) {
        int c = tx + 16 * i;
        As[ty][c] = (r < M) ? A[(size_t)r * K + c] : 0.f;
    }
    __syncthreads();
    float acc = 0.f;
#pragma unroll 8
    for (int k = 0; k < K; k++) acc += As[ty][k] * Bs[k * 16 + tx];
    if (r < M) {
        float v = acc;
        if (bias) v += bias[tx];
        C[(size_t)r * 16 + tx] = v;
    }
}

// ---------------- edge scores layer 1: warp per edge, 4 heads x 32 ch --------------
__global__ void edge_scores1_kernel(const float* __restrict__ att) {
    int w = blockIdx.x * (blockDim.x >> 5) + (threadIdx.x >> 5);
    if (w >= NE) return;
    int lane = threadIdx.x & 31;
    int s = g_src[w], d = g_dst[w];
    const float* xls = g_xl1 + (size_t)s * D1;
    const float* xrd = g_xr1 + (size_t)d * D1;
    float ph[HEADS];
#pragma unroll
    for (int j = 0; j < HEADS; j++) {
        int c = j * 32 + lane;
        float v = xls[c] + xrd[c];
        v = (v > 0.f) ? v : NEG_SLOPE * v;
        float p = v * __ldg(&att[c]);
#pragma unroll
        for (int o = 16; o > 0; o >>= 1) p += __shfl_xor_sync(0xffffffffu, p, o);
        ph[j] = p;
    }
    if (lane == 0) {
#pragma unroll
        for (int j = 0; j < HEADS; j++) g_scores1[(size_t)w * HEADS + j] = ph[j];
    }
}

// ---------------- edge scores layer 2: half-warp per edge, 16 ch -------------------
__global__ void edge_scores2_kernel(const float* __restrict__ att) {
    int w = blockIdx.x * (blockDim.x >> 5) + (threadIdx.x >> 5);
    int lane = threadIdx.x & 31;
    int sub = lane >> 4;
    int c = lane & 15;
    int e = w * 2 + sub;
    float p = 0.f;
    if (e < NE) {
        int s = g_src[e], d = g_dst[e];
        float v = g_xl2[(size_t)s * NCLS + c] + g_xr2[(size_t)d * NCLS + c];
        v = (v > 0.f) ? v : NEG_SLOPE * v;
        p = v * __ldg(&att[c]);
    }
#pragma unroll
    for (int o = 8; o > 0; o >>= 1) p += __shfl_xor_sync(0xffffffffu, p, o);
    if (c == 0 && e < NE) g_scores2[e] = p;
}

// ---------------- top-k + dual masked softmax: thread per (node, head) -------------
// layer: 1 -> (g_scores1, g_alpha1, g_alphan1, H=4), 2 -> (g_scores2, ..., H=1)
__global__ void topk_alpha_kernel(int layer, const int* __restrict__ kptr) {
    const int H = (layer == 1) ? HEADS : 1;
    const float* scores = (layer == 1) ? (const float*)g_scores1 : (const float*)g_scores2;
    float* alpha  = (layer == 1) ? g_alpha1  : g_alpha2;
    float* alphan = (layer == 1) ? g_alphan1 : g_alphan2;

    int t = blockIdx.x * blockDim.x + threadIdx.x;
    if (t >= NN * H) return;
    int n = t / H, h = t - n * H;
    int beg = g_offs[n], cnt = g_counts[n];
    if (cnt == 0) return;
    int k = *kptr;
    if (k > KMAX) k = KMAX;
    if (k < 0) k = 0;

    float ts[KMAX];
    int   te[KMAX];
    int m = 0;
    for (int p = 0; p < cnt; p++) {
        int e = g_elist[beg + p];
        float s = scores[(size_t)e * H + h];
        if (m < k) {
            int i = m++;
            while (i > 0 && (s > ts[i - 1] || (s == ts[i - 1] && e < te[i - 1]))) {
                ts[i] = ts[i - 1]; te[i] = te[i - 1]; i--;
            }
            ts[i] = s; te[i] = e;
        } else if (k > 0) {
            if (s > ts[k - 1] || (s == ts[k - 1] && e < te[k - 1])) {
                int i = k - 1;
                while (i > 0 && (s > ts[i - 1] || (s == ts[i - 1] && e < te[i - 1]))) {
                    ts[i] = ts[i - 1]; te[i] = te[i - 1]; i--;
                }
                ts[i] = s; te[i] = e;
            }
        }
    }
    bool all_kept = (cnt <= k);
    float thr_s = (m > 0) ? ts[m - 1] : __int_as_float(0x7f800000);
    int   thr_e = (m > 0) ? te[m - 1] : -1;
    float mk = (m > 0) ? ts[0] : 0.f;

    float mn = -__int_as_float(0x7f800000);
    if (!all_kept) {
        for (int p = 0; p < cnt; p++) {
            int e = g_elist[beg + p];
            float s = scores[(size_t)e * H + h];
            bool kept = (s > thr_s) || (s == thr_s && e <= thr_e);
            if (!kept && s > mn) mn = s;
        }
    }
    if (!isfinite(mn)) mn = 0.f;

    float sumk = 0.f, sumn = 0.f;
    for (int p = 0; p < cnt; p++) {
        int e = g_elist[beg + p];
        float s = scores[(size_t)e * H + h];
        bool kept = all_kept || (s > thr_s) || (s == thr_s && e <= thr_e);
        if (kept) sumk += expf(s - mk);
        else      sumn += expf(s - mn);
    }
    float invk = 1.f / (sumk + 1e-16f);
    float invn = 1.f / (sumn + 1e-16f);
    for (int p = 0; p < cnt; p++) {
        int e = g_elist[beg + p];
        float s = scores[(size_t)e * H + h];
        bool kept = all_kept || (s > thr_s) || (s == thr_s && e <= thr_e);
        size_t idx = (size_t)e * H + h;
        if (kept) { alpha[idx] = expf(s - mk) * invk; alphan[idx] = 0.f; }
        else      { alpha[idx] = 0.f;                 alphan[idx] = expf(s - mn) * invn; }
    }
}

// ---------------- aggregation layer 1: warp per (node, head), lane = channel -------
__global__ void aggregate1_kernel(const float* __restrict__ b1) {
    int w = blockIdx.x * (blockDim.x >> 5) + (threadIdx.x >> 5);
    if (w >= NN * HEADS) return;
    int lane = threadIdx.x & 31;
    int n = w >> 2, h = w & 3;
    int beg = g_offs[n], cnt = g_counts[n];
    float acc = 0.f, accn = 0.f;
    for (int p = 0; p < cnt; p++) {
        int e = g_elist[beg + p];
        float a  = g_alpha1[(size_t)e * HEADS + h];
        float an = g_alphan1[(size_t)e * HEADS + h];
        int s = g_src[e];
        float xv = g_xl1[(size_t)s * D1 + h * 32 + lane];
        acc  += a * xv;
        accn += an * xv;
    }
    int c = h * 32 + lane;
    float bb = b1[c];
    float o = acc + bb;
    g_h1[(size_t)n * D1 + c]     = (o > 0.f) ? o : expm1f(o);
    g_noise1[(size_t)n * D1 + c] = accn + bb;
}

// ---------------- aggregation layer 2: half-warp per node, lane = class ------------
__global__ void aggregate2_kernel(const float* __restrict__ b2) {
    int w = blockIdx.x * (blockDim.x >> 5) + (threadIdx.x >> 5);
    int lane = threadIdx.x & 31;
    int sub = lane >> 4;
    int c = lane & 15;
    int n = w * 2 + sub;
    if (n >= NN) return;
    int beg = g_offs[n], cnt = g_counts[n];
    float acc = 0.f, accn = 0.f;
    for (int p = 0; p < cnt; p++) {
        int e = g_elist[beg + p];
        float a  = g_alpha2[e];
        float an = g_alphan2[e];
        int s = g_src[e];
        float xv = g_xl2[(size_t)s * NCLS + c];
        acc  += a * xv;
        accn += an * xv;
    }
    float bb = b2[c];
    g_out2[(size_t)n * NCLS + c]   = acc + bb;
    g_noise2[(size_t)n * NCLS + c] = accn + bb;
}

// ---------------- log_softmax over 16 classes, thread per row ----------------------
// tag: 0 -> in=g_out2, 1 -> in=g_n1, 2 -> in=g_noise2
__global__ void log_softmax16_kernel(int tag, float* __restrict__ out) {
    const float* in = (tag == 0) ? (const float*)g_out2
                    : (tag == 1) ? (const float*)g_n1 : (const float*)g_noise2;
    int r = blockIdx.x * blockDim.x + threadIdx.x;
    if (r >= NN) return;
    float v[NCLS];
    float mx = -3.4e38f;
#pragma unroll
    for (int c = 0; c < NCLS; c++) { v[c] = in[(size_t)r * NCLS + c]; mx = fmaxf(mx, v[c]); }
    float s = 0.f;
#pragma unroll
    for (int c = 0; c < NCLS; c++) s += expf(v[c] - mx);
    float ls = mx + logf(s);
#pragma unroll
    for (int c = 0; c < NCLS; c++) out[(size_t)r * NCLS + c] = v[c] - ls;
}

// ---------------- host ----------------
extern "C" void kernel_launch(void* const* d_in, const int* in_sizes, int n_in,
                              void* d_out, int out_size) {
    const float* x      = (const float*)d_in[0];
    const int*   ei     = (const int*)d_in[1];      // int32 (JAX x64 disabled)
    const int*   kptr   = (const int*)d_in[2];
    const float* Wl1    = (const float*)d_in[3];
    const float* Wr1    = (const float*)d_in[4];
    const float* att1   = (const float*)d_in[5];
    const float* b1     = (const float*)d_in[6];
    const float* Wl2    = (const float*)d_in[7];
    const float* Wr2    = (const float*)d_in[8];
    const float* att2   = (const float*)d_in[9];
    const float* b2     = (const float*)d_in[10];
    const float* lin1_w = (const float*)d_in[11];
    const float* lin1_b = (const float*)d_in[12];
    const float* lin2_w = (const float*)d_in[13];
    const float* lin2_b = (const float*)d_in[14];
    float* out = (float*)d_out;

    // --- CSR build ---
    init_csr_kernel<<<(NN + 255) / 256, 256>>>();
    convert_edges_kernel<<<(NE + 255) / 256, 256>>>(ei);
    count_kernel<<<(NE + 255) / 256, 256>>>();
    scan_kernel<<<1, 1024>>>();
    scatter_kernel<<<(NE + 255) / 256, 256>>>();

    // --- layer 1 projections ---
    dim3 g1((NN + 63) / 64, 2);
    sgemm128_kernel<<<g1, 256>>>(0, x, Wl1, nullptr, 0);
    sgemm128_kernel<<<g1, 256>>>(1, x, Wr1, nullptr, 0);

    // --- layer 1 attention ---
    edge_scores1_kernel<<<(NE + 7) / 8, 256>>>(att1);
    topk_alpha_kernel<<<(NN * HEADS + 255) / 256, 256>>>(1, kptr);
    aggregate1_kernel<<<(NN * HEADS + 7) / 8, 256>>>(b1);

    // --- noise MLP: n1 = elu(noise1 @ lin1_w + lin1_b) @ lin2_w + lin2_b ---
    sgemm128_kernel<<<g1, 256>>>(2, nullptr, lin1_w, lin1_b, 1);
    sgemm_n16_kernel<<<(NN + 15) / 16, 256>>>(0, lin2_w, lin2_b);

    // --- layer 2 projections ---
    sgemm_n16_kernel<<<(NN + 15) / 16, 256>>>(1, Wl2, nullptr);
    sgemm_n16_kernel<<<(NN + 15) / 16, 256>>>(2, Wr2, nullptr);

    // --- layer 2 attention ---
    edge_scores2_kernel<<<((NE + 1) / 2 + 7) / 8, 256>>>(att2);
    topk_alpha_kernel<<<(NN + 255) / 256, 256>>>(2, kptr);
    aggregate2_kernel<<<((NN + 1) / 2 + 7) / 8, 256>>>(b2);

    // --- outputs ---
    log_softmax16_kernel<<<(NN + 255) / 256, 256>>>(0, out);
    log_softmax16_kernel<<<(NN + 255) / 256, 256>>>(1, out + (size_t)NN * NCLS);
    log_softmax16_kernel<<<(NN + 255) / 256, 256>>>(2, out + 2 * (size_t)NN * NCLS);
}

// round 5
// speedup vs baseline: 1.3948x; 1.3948x over previous
#include <cuda_runtime.h>
#include <math.h>
#include <stdint.h>

#define NN    50000
#define NE    800000
#define FIN   128
#define HID   32
#define HEADS 4
#define D1    128      // HEADS*HID
#define NCLS  16
#define MLPH  128
#define KMAX  16
#define NEG_SLOPE 0.2f
#define NBLK_SCAN 196  // ceil(NN/256)

// ---------------- scratch (static device memory; no runtime allocs) ----------------
__device__ int   g_src[NE], g_dst[NE];
__device__ int   g_epos[NE];            // edge id -> CSR position
__device__ int   g_eid[NE];             // CSR position -> edge id (for tie-break)
__device__ int   g_srcc[NE];            // CSR position -> src node
__device__ int   g_counts[NN], g_offs[NN], g_cursor[NN];
__device__ int   g_blocksum[NBLK_SCAN], g_blockbase[NBLK_SCAN];
__device__ __align__(16) float g_xl1[(size_t)NN * D1];
__device__ __align__(16) float g_xr1[(size_t)NN * D1];
__device__ __align__(16) float g_scores1[(size_t)NE * HEADS];                 // CSR order
__device__ __align__(16) float g_alpha1[(size_t)NE * HEADS];
__device__ __align__(16) float g_alphan1[(size_t)NE * HEADS];
__device__ __align__(16) float g_h1[(size_t)NN * D1];
__device__ __align__(16) float g_noise1[(size_t)NN * D1];
__device__ __align__(16) float g_mlph[(size_t)NN * MLPH];
__device__ __align__(16) float g_n1[NN * NCLS];
__device__ __align__(16) float g_xl2[NN * NCLS];
__device__ __align__(16) float g_xr2[NN * NCLS];
__device__ __align__(16) float g_scores2[NE];
__device__ __align__(16) float g_alpha2[NE];
__device__ __align__(16) float g_alphan2[NE];
__device__ __align__(16) float g_out2[NN * NCLS];
__device__ __align__(16) float g_noise2[NN * NCLS];

// ---------------- CSR build ----------------
__global__ void init_csr_kernel() {
    int i = blockIdx.x * blockDim.x + threadIdx.x;
    if (i < NN) { g_counts[i] = 0; g_cursor[i] = 0; }
}

// edge_index is int32; fuse convert + clamp + count
__global__ void convert_count_kernel(const int* __restrict__ ei) {
    int e = blockIdx.x * blockDim.x + threadIdx.x;
    if (e < NE) {
        int s = min(max(ei[e], 0), NN - 1);
        int d = min(max(ei[NE + e], 0), NN - 1);
        g_src[e] = s;
        g_dst[e] = d;
        atomicAdd(&g_counts[d], 1);
    }
}

__global__ void block_sum_kernel() {
    __shared__ int sh[256];
    int b = blockIdx.x, t = threadIdx.x;
    int i = b * 256 + t;
    sh[t] = (i < NN) ? g_counts[i] : 0;
    __syncthreads();
    for (int o = 128; o > 0; o >>= 1) {
        if (t < o) sh[t] += sh[t + o];
        __syncthreads();
    }
    if (t == 0) g_blocksum[b] = sh[0];
}

__global__ void scan_partials_kernel() {
    __shared__ int sh[256];
    int t = threadIdx.x;
    int v = (t < NBLK_SCAN) ? g_blocksum[t] : 0;
    sh[t] = v;
    __syncthreads();
    for (int o = 1; o < 256; o <<= 1) {
        int u = (t >= o) ? sh[t - o] : 0;
        __syncthreads();
        sh[t] += u;
        __syncthreads();
    }
    if (t < NBLK_SCAN) g_blockbase[t] = sh[t] - v;   // exclusive
}

__global__ void scan_final_kernel() {
    __shared__ int sh[256];
    int b = blockIdx.x, t = threadIdx.x;
    int i = b * 256 + t;
    int v = (i < NN) ? g_counts[i] : 0;
    sh[t] = v;
    __syncthreads();
    for (int o = 1; o < 256; o <<= 1) {
        int u = (t >= o) ? sh[t - o] : 0;
        __syncthreads();
        sh[t] += u;
        __syncthreads();
    }
    if (i < NN) g_offs[i] = g_blockbase[b] + sh[t] - v;  // exclusive global
}

__global__ void scatter_kernel() {
    int e = blockIdx.x * blockDim.x + threadIdx.x;
    if (e < NE) {
        int d = g_dst[e];
        int pos = g_offs[d] + atomicAdd(&g_cursor[d], 1);
        g_epos[e] = pos;
        g_eid[pos] = e;
        g_srcc[pos] = g_src[e];
    }
}

// ---------------- SGEMM: C[M,128tile] = A[M,128] @ B[128,64tile] (+bias, act) ------
// BM=128, BN=64, BK=16, 256 threads, 8x4 microtile.
// NOTE: As padded by +4 so each row (132 floats = 528 B) stays 16-byte aligned
// for the float4 shared-memory reads (the +1 pad caused misaligned LDS.128).
__global__ void sgemm128_kernel(int tag, const float* __restrict__ Aparam,
                                const float* __restrict__ B1,
                                const float* __restrict__ B2,
                                const float* __restrict__ bias, int act) {
    const int M = NN, N = 128, K = 128;
    const int BM = 128, BK = 16;
    __shared__ float As[BK][BM + 4];
    __shared__ float Bs[BK][64];
    int yy = blockIdx.y;
    const float* A = (tag == 2) ? (const float*)g_noise1 : Aparam;
    const float* B;
    float* C;
    int col0;
    if (tag == 0) {
        if (yy < 2) { B = B1; C = g_xl1; col0 = yy * 64; }
        else        { B = B2; C = g_xr1; col0 = (yy - 2) * 64; }
    } else {
        B = B1; C = g_mlph; col0 = yy * 64;
    }
    int row0 = blockIdx.x * BM;
    int tid = threadIdx.x;                 // 256
    int tx = tid % 16, ty = tid / 16;      // 16 cols x 16 rows of (8x4)
    int lr = tid / 16, lc = tid % 16;      // A load
    int br = tid / 64, bc = tid % 64;      // B load
    float acc[8][4] = {};
    for (int k0 = 0; k0 < K; k0 += BK) {
#pragma unroll
        for (int i = 0; i < 8; i++) {
            int r = row0 + lr + 16 * i;
            float v = 0.f;
            if (r < M) v = A[(size_t)r * K + k0 + lc];
            As[lc][lr + 16 * i] = v;
        }
#pragma unroll
        for (int i = 0; i < 4; i++) {
            int kr = k0 + br + 4 * i;
            Bs[br + 4 * i][bc] = B[(size_t)kr * N + col0 + bc];
        }
        __syncthreads();
#pragma unroll
        for (int kk = 0; kk < BK; kk++) {
            float a[8], b[4];
            float4 a0 = *(const float4*)&As[kk][ty * 8];
            float4 a1 = *(const float4*)&As[kk][ty * 8 + 4];
            a[0]=a0.x; a[1]=a0.y; a[2]=a0.z; a[3]=a0.w;
            a[4]=a1.x; a[5]=a1.y; a[6]=a1.z; a[7]=a1.w;
            float4 b0 = *(const float4*)&Bs[kk][tx * 4];
            b[0]=b0.x; b[1]=b0.y; b[2]=b0.z; b[3]=b0.w;
#pragma unroll
            for (int i = 0; i < 8; i++)
#pragma unroll
                for (int j = 0; j < 4; j++) acc[i][j] += a[i] * b[j];
        }
        __syncthreads();
    }
#pragma unroll
    for (int i = 0; i < 8; i++) {
        int r = row0 + ty * 8 + i;
        if (r >= M) continue;
#pragma unroll
        for (int j = 0; j < 4; j++) {
            int c = col0 + tx * 4 + j;
            float v = acc[i][j];
            if (bias) v += bias[c];
            if (act == 1) v = (v > 0.f) ? v : expm1f(v);
            C[(size_t)r * N + c] = v;
        }
    }
}

// N=16 GEMM: C[M,16] = g_mlph[M,128] @ B[128,16] + bias
__global__ void sgemm_n16_kernel(const float* __restrict__ B,
                                 const float* __restrict__ bias) {
    const int M = NN, K = 128;
    __shared__ float Bs[K * 16];
    __shared__ float As[16][K];
    int tid = threadIdx.x;              // 256
    int tx = tid % 16, ty = tid / 16;
    for (int i = tid; i < K * 16; i += 256) Bs[i] = B[i];
    int r = blockIdx.x * 16 + ty;
#pragma unroll
    for (int i = 0; i < 8; i++) {
        int c = tx + 16 * i;
        As[ty][c] = (r < M) ? g_mlph[(size_t)r * K + c] : 0.f;
    }
    __syncthreads();
    float acc = 0.f;
#pragma unroll 8
    for (int k = 0; k < K; k++) acc += As[ty][k] * Bs[k * 16 + tx];
    if (r < M) g_n1[(size_t)r * 16 + tx] = acc + bias[tx];
}

// dual N=16 GEMM: xl2 = h1 @ Wl2, xr2 = h1 @ Wr2 (A read once)
__global__ void sgemm_n16_dual_kernel(const float* __restrict__ Bl,
                                      const float* __restrict__ Br) {
    const int M = NN, K = 128;
    __shared__ float Bsl[K * 16];
    __shared__ float Bsr[K * 16];
    __shared__ float As[16][K];
    int tid = threadIdx.x;
    int tx = tid % 16, ty = tid / 16;
    for (int i = tid; i < K * 16; i += 256) { Bsl[i] = Bl[i]; Bsr[i] = Br[i]; }
    int r = blockIdx.x * 16 + ty;
#pragma unroll
    for (int i = 0; i < 8; i++) {
        int c = tx + 16 * i;
        As[ty][c] = (r < M) ? g_h1[(size_t)r * K + c] : 0.f;
    }
    __syncthreads();
    float accl = 0.f, accr = 0.f;
#pragma unroll 8
    for (int k = 0; k < K; k++) {
        float a = As[ty][k];
        accl += a * Bsl[k * 16 + tx];
        accr += a * Bsr[k * 16 + tx];
    }
    if (r < M) {
        g_xl2[(size_t)r * 16 + tx] = accl;
        g_xr2[(size_t)r * 16 + tx] = accr;
    }
}

// ---------------- edge scores layer 1: warp per edge, float4 lanes -----------------
__global__ void edge_scores1_kernel(const float* __restrict__ att) {
    int w = blockIdx.x * (blockDim.x >> 5) + (threadIdx.x >> 5);
    if (w >= NE) return;
    int lane = threadIdx.x & 31;
    int s = g_src[w], d = g_dst[w];
    float4 a = *(const float4*)(g_xl1 + (size_t)s * D1 + lane * 4);
    float4 b = *(const float4*)(g_xr1 + (size_t)d * D1 + lane * 4);
    float4 t = __ldg((const float4*)att + lane);
    float vx = a.x + b.x; vx = (vx > 0.f) ? vx : NEG_SLOPE * vx;
    float vy = a.y + b.y; vy = (vy > 0.f) ? vy : NEG_SLOPE * vy;
    float vz = a.z + b.z; vz = (vz > 0.f) ? vz : NEG_SLOPE * vz;
    float vw = a.w + b.w; vw = (vw > 0.f) ? vw : NEG_SLOPE * vw;
    float p = vx * t.x + vy * t.y + vz * t.z + vw * t.w;
    p += __shfl_xor_sync(0xffffffffu, p, 1);
    p += __shfl_xor_sync(0xffffffffu, p, 2);
    p += __shfl_xor_sync(0xffffffffu, p, 4);
    if ((lane & 7) == 0) {
        int pos = g_epos[w];
        g_scores1[(size_t)pos * HEADS + (lane >> 3)] = p;
    }
}

// ---------------- edge scores layer 2: warp handles 8 edges, float4 lanes ----------
__global__ void edge_scores2_kernel(const float* __restrict__ att) {
    int w = blockIdx.x * (blockDim.x >> 5) + (threadIdx.x >> 5);
    int lane = threadIdx.x & 31;
    int sub = lane >> 2;          // 0..7 edge within warp
    int i = lane & 3;             // float4 chunk
    int e = w * 8 + sub;
    float p = 0.f;
    if (e < NE) {
        int s = g_src[e], d = g_dst[e];
        float4 a = *(const float4*)(g_xl2 + (size_t)s * NCLS + i * 4);
        float4 b = *(const float4*)(g_xr2 + (size_t)d * NCLS + i * 4);
        float4 t = __ldg((const float4*)att + i);
        float vx = a.x + b.x; vx = (vx > 0.f) ? vx : NEG_SLOPE * vx;
        float vy = a.y + b.y; vy = (vy > 0.f) ? vy : NEG_SLOPE * vy;
        float vz = a.z + b.z; vz = (vz > 0.f) ? vz : NEG_SLOPE * vz;
        float vw = a.w + b.w; vw = (vw > 0.f) ? vw : NEG_SLOPE * vw;
        p = vx * t.x + vy * t.y + vz * t.z + vw * t.w;
    }
    p += __shfl_xor_sync(0xffffffffu, p, 1);
    p += __shfl_xor_sync(0xffffffffu, p, 2);
    if (i == 0 && e < NE) g_scores2[g_epos[e]] = p;
}

// ---------------- top-k + dual masked softmax: thread per (node, head) -------------
__global__ void topk_alpha_kernel(int layer, const int* __restrict__ kptr) {
    const int H = (layer == 1) ? HEADS : 1;
    const float* scores = (layer == 1) ? (const float*)g_scores1 : (const float*)g_scores2;
    float* alpha  = (layer == 1) ? g_alpha1  : g_alpha2;
    float* alphan = (layer == 1) ? g_alphan1 : g_alphan2;

    int t = blockIdx.x * blockDim.x + threadIdx.x;
    if (t >= NN * H) return;
    int n = t / H, h = t - n * H;
    int beg = g_offs[n], cnt = g_counts[n];
    if (cnt == 0) return;
    int k = *kptr;
    if (k > KMAX) k = KMAX;
    if (k < 0) k = 0;

    float ts[KMAX];
    int   te[KMAX];
    int m = 0;
    for (int p = 0; p < cnt; p++) {
        int idx = beg + p;
        float s = scores[(size_t)idx * H + h];
        int e = g_eid[idx];
        if (m < k) {
            int i = m++;
            while (i > 0 && (s > ts[i - 1] || (s == ts[i - 1] && e < te[i - 1]))) {
                ts[i] = ts[i - 1]; te[i] = te[i - 1]; i--;
            }
            ts[i] = s; te[i] = e;
        } else if (k > 0) {
            if (s > ts[k - 1] || (s == ts[k - 1] && e < te[k - 1])) {
                int i = k - 1;
                while (i > 0 && (s > ts[i - 1] || (s == ts[i - 1] && e < te[i - 1]))) {
                    ts[i] = ts[i - 1]; te[i] = te[i - 1]; i--;
                }
                ts[i] = s; te[i] = e;
            }
        }
    }
    bool all_kept = (cnt <= k);
    float thr_s = (m > 0) ? ts[m - 1] : __int_as_float(0x7f800000);
    int   thr_e = (m > 0) ? te[m - 1] : -1;
    float mk = (m > 0) ? ts[0] : 0.f;

    float mn = -__int_as_float(0x7f800000);
    if (!all_kept) {
        for (int p = 0; p < cnt; p++) {
            int idx = beg + p;
            float s = scores[(size_t)idx * H + h];
            int e = g_eid[idx];
            bool kept = (s > thr_s) || (s == thr_s && e <= thr_e);
            if (!kept && s > mn) mn = s;
        }
    }
    if (!isfinite(mn)) mn = 0.f;

    float sumk = 0.f, sumn = 0.f;
    for (int p = 0; p < cnt; p++) {
        int idx = beg + p;
        float s = scores[(size_t)idx * H + h];
        int e = g_eid[idx];
        bool kept = all_kept || (s > thr_s) || (s == thr_s && e <= thr_e);
        if (kept) sumk += expf(s - mk);
        else      sumn += expf(s - mn);
    }
    float invk = 1.f / (sumk + 1e-16f);
    float invn = 1.f / (sumn + 1e-16f);
    for (int p = 0; p < cnt; p++) {
        int idx = beg + p;
        float s = scores[(size_t)idx * H + h];
        int e = g_eid[idx];
        bool kept = all_kept || (s > thr_s) || (s == thr_s && e <= thr_e);
        size_t o = (size_t)idx * H + h;
        if (kept) { alpha[o] = expf(s - mk) * invk; alphan[o] = 0.f; }
        else      { alpha[o] = 0.f;                 alphan[o] = expf(s - mn) * invn; }
    }
}

// ---------------- aggregation layer 1: warp per (node, head), lane = channel -------
__global__ void aggregate1_kernel(const float* __restrict__ b1) {
    int w = blockIdx.x * (blockDim.x >> 5) + (threadIdx.x >> 5);
    if (w >= NN * HEADS) return;
    int lane = threadIdx.x & 31;
    int n = w >> 2, h = w & 3;
    int beg = g_offs[n], cnt = g_counts[n];
    float acc = 0.f, accn = 0.f;
    for (int p = 0; p < cnt; p++) {
        int idx = beg + p;
        float a  = g_alpha1[(size_t)idx * HEADS + h];
        float an = g_alphan1[(size_t)idx * HEADS + h];
        int s = g_srcc[idx];
        float xv = g_xl1[(size_t)s * D1 + h * 32 + lane];
        acc  += a * xv;
        accn += an * xv;
    }
    int c = h * 32 + lane;
    float bb = b1[c];
    float o = acc + bb;
    g_h1[(size_t)n * D1 + c]     = (o > 0.f) ? o : expm1f(o);
    g_noise1[(size_t)n * D1 + c] = accn + bb;
}

// ---------------- aggregation layer 2: half-warp per node, lane = class ------------
__global__ void aggregate2_kernel(const float* __restrict__ b2) {
    int w = blockIdx.x * (blockDim.x >> 5) + (threadIdx.x >> 5);
    int lane = threadIdx.x & 31;
    int sub = lane >> 4;
    int c = lane & 15;
    int n = w * 2 + sub;
    if (n >= NN) return;
    int beg = g_offs[n], cnt = g_counts[n];
    float acc = 0.f, accn = 0.f;
    for (int p = 0; p < cnt; p++) {
        int idx = beg + p;
        float a  = g_alpha2[idx];
        float an = g_alphan2[idx];
        int s = g_srcc[idx];
        float xv = g_xl2[(size_t)s * NCLS + c];
        acc  += a * xv;
        accn += an * xv;
    }
    float bb = b2[c];
    g_out2[(size_t)n * NCLS + c]   = acc + bb;
    g_noise2[(size_t)n * NCLS + c] = accn + bb;
}

// ---------------- log_softmax over 16 classes, thread per row, 3 inputs ------------
__global__ void log_softmax16_kernel(float* __restrict__ out) {
    int r = blockIdx.x * blockDim.x + threadIdx.x;
    if (r >= 3 * NN) return;
    const float* in = (r < NN) ? (const float*)g_out2
                    : (r < 2 * NN) ? (const float*)g_n1 - (size_t)NN * NCLS
                    : (const float*)g_noise2 - 2 * (size_t)NN * NCLS;
    float v[NCLS];
    float mx = -3.4e38f;
#pragma unroll
    for (int c = 0; c < NCLS; c++) { v[c] = in[(size_t)r * NCLS + c]; mx = fmaxf(mx, v[c]); }
    float s = 0.f;
#pragma unroll
    for (int c = 0; c < NCLS; c++) s += expf(v[c] - mx);
    float ls = mx + logf(s);
#pragma unroll
    for (int c = 0; c < NCLS; c++) out[(size_t)r * NCLS + c] = v[c] - ls;
}

// ---------------- host ----------------
extern "C" void kernel_launch(void* const* d_in, const int* in_sizes, int n_in,
                              void* d_out, int out_size) {
    const float* x      = (const float*)d_in[0];
    const int*   ei     = (const int*)d_in[1];
    const int*   kptr   = (const int*)d_in[2];
    const float* Wl1    = (const float*)d_in[3];
    const float* Wr1    = (const float*)d_in[4];
    const float* att1   = (const float*)d_in[5];
    const float* b1     = (const float*)d_in[6];
    const float* Wl2    = (const float*)d_in[7];
    const float* Wr2    = (const float*)d_in[8];
    const float* att2   = (const float*)d_in[9];
    const float* b2     = (const float*)d_in[10];
    const float* lin1_w = (const float*)d_in[11];
    const float* lin1_b = (const float*)d_in[12];
    const float* lin2_w = (const float*)d_in[13];
    const float* lin2_b = (const float*)d_in[14];
    float* out = (float*)d_out;

    // --- CSR build ---
    init_csr_kernel<<<(NN + 255) / 256, 256>>>();
    convert_count_kernel<<<(NE + 255) / 256, 256>>>(ei);
    block_sum_kernel<<<NBLK_SCAN, 256>>>();
    scan_partials_kernel<<<1, 256>>>();
    scan_final_kernel<<<NBLK_SCAN, 256>>>();
    scatter_kernel<<<(NE + 255) / 256, 256>>>();

    // --- layer 1 projections (fused xl1+xr1) ---
    dim3 gProj((NN + 127) / 128, 4);
    sgemm128_kernel<<<gProj, 256>>>(0, x, Wl1, Wr1, nullptr, 0);

    // --- layer 1 attention ---
    edge_scores1_kernel<<<(NE + 7) / 8, 256>>>(att1);
    topk_alpha_kernel<<<(NN * HEADS + 255) / 256, 256>>>(1, kptr);
    aggregate1_kernel<<<(NN * HEADS + 7) / 8, 256>>>(b1);

    // --- noise MLP ---
    dim3 gMlp((NN + 127) / 128, 2);
    sgemm128_kernel<<<gMlp, 256>>>(2, nullptr, lin1_w, nullptr, lin1_b, 1);
    sgemm_n16_kernel<<<(NN + 15) / 16, 256>>>(lin2_w, lin2_b);

    // --- layer 2 projections (fused xl2+xr2) ---
    sgemm_n16_dual_kernel<<<(NN + 15) / 16, 256>>>(Wl2, Wr2);

    // --- layer 2 attention ---
    edge_scores2_kernel<<<((NE + 7) / 8 + 7) / 8, 256>>>(att2);
    topk_alpha_kernel<<<(NN + 255) / 256, 256>>>(2, kptr);
    aggregate2_kernel<<<((NN + 1) / 2 + 7) / 8, 256>>>(b2);

    // --- outputs (single fused log_softmax over 3*NN rows) ---
    log_softmax16_kernel<<<(3 * NN + 255) / 256, 256>>>(out);
}

// round 6
// speedup vs baseline: 1.4029x; 1.0058x over previous
#include <cuda_runtime.h>
#include <math.h>
#include <stdint.h>

#define NN    50000
#define NE    800000
#define FIN   128
#define HID   32
#define HEADS 4
#define D1    128      // HEADS*HID
#define NCLS  16
#define MLPH  128
#define KMAX  16
#define NEG_SLOPE 0.2f
#define NBLK_SCAN 196  // ceil(NN/256)

// ---------------- scratch (static device memory; no runtime allocs) ----------------
__device__ int   g_src[NE], g_dst[NE];
__device__ int   g_eid[NE];             // CSR position -> edge id (tie-break)
__device__ int   g_srcc[NE];            // CSR position -> src node
__device__ int   g_dstc[NE];            // CSR position -> dst node
__device__ int   g_counts[NN], g_offs[NN], g_cursor[NN];
__device__ int   g_blocksum[NBLK_SCAN], g_blockbase[NBLK_SCAN];
__device__ __align__(16) float g_xl1[(size_t)NN * D1];
__device__ __align__(16) float g_xr1[(size_t)NN * D1];
__device__ __align__(16) float g_scores1[(size_t)NE * HEADS];   // CSR order
__device__ __align__(16) float g_alpha1[(size_t)NE * HEADS];
__device__ __align__(16) float g_alphan1[(size_t)NE * HEADS];
__device__ __align__(16) float g_h1[(size_t)NN * D1];
__device__ __align__(16) float g_noise1[(size_t)NN * D1];
__device__ __align__(16) float g_mlph[(size_t)NN * MLPH];
__device__ __align__(16) float g_n1[NN * NCLS];
__device__ __align__(16) float g_xl2[NN * NCLS];
__device__ __align__(16) float g_xr2[NN * NCLS];
__device__ __align__(16) float g_scores2[NE];
__device__ __align__(16) float g_alpha2[NE];
__device__ __align__(16) float g_alphan2[NE];
__device__ __align__(16) float g_out2[NN * NCLS];
__device__ __align__(16) float g_noise2[NN * NCLS];

// ---------------- CSR build ----------------
__global__ void init_csr_kernel() {
    int i = blockIdx.x * blockDim.x + threadIdx.x;
    if (i < NN) { g_counts[i] = 0; g_cursor[i] = 0; }
}

__global__ void convert_count_kernel(const int* __restrict__ ei) {
    int e = blockIdx.x * blockDim.x + threadIdx.x;
    if (e < NE) {
        int s = min(max(ei[e], 0), NN - 1);
        int d = min(max(ei[NE + e], 0), NN - 1);
        g_src[e] = s;
        g_dst[e] = d;
        atomicAdd(&g_counts[d], 1);
    }
}

__global__ void block_sum_kernel() {
    __shared__ int sh[256];
    int b = blockIdx.x, t = threadIdx.x;
    int i = b * 256 + t;
    sh[t] = (i < NN) ? g_counts[i] : 0;
    __syncthreads();
    for (int o = 128; o > 0; o >>= 1) {
        if (t < o) sh[t] += sh[t + o];
        __syncthreads();
    }
    if (t == 0) g_blocksum[b] = sh[0];
}

__global__ void scan_partials_kernel() {
    __shared__ int sh[256];
    int t = threadIdx.x;
    int v = (t < NBLK_SCAN) ? g_blocksum[t] : 0;
    sh[t] = v;
    __syncthreads();
    for (int o = 1; o < 256; o <<= 1) {
        int u = (t >= o) ? sh[t - o] : 0;
        __syncthreads();
        sh[t] += u;
        __syncthreads();
    }
    if (t < NBLK_SCAN) g_blockbase[t] = sh[t] - v;
}

__global__ void scan_final_kernel() {
    __shared__ int sh[256];
    int b = blockIdx.x, t = threadIdx.x;
    int i = b * 256 + t;
    int v = (i < NN) ? g_counts[i] : 0;
    sh[t] = v;
    __syncthreads();
    for (int o = 1; o < 256; o <<= 1) {
        int u = (t >= o) ? sh[t - o] : 0;
        __syncthreads();
        sh[t] += u;
        __syncthreads();
    }
    if (i < NN) g_offs[i] = g_blockbase[b] + sh[t] - v;
}

__global__ void scatter_kernel() {
    int e = blockIdx.x * blockDim.x + threadIdx.x;
    if (e < NE) {
        int d = g_dst[e];
        int pos = g_offs[d] + atomicAdd(&g_cursor[d], 1);
        g_eid[pos] = e;
        g_srcc[pos] = g_src[e];
        g_dstc[pos] = d;
    }
}

// ---------------- SGEMM: 128x128 tile, 8x8 microtile, 256 threads ------------------
// C[M,128] = A[M,128] @ B[128,128] (+bias, act)
// tag 0: yy==0 -> B1=Wl1 -> g_xl1 ; yy==1 -> B2=Wr1 -> g_xr1 (A = Aparam)
// tag 2: A = g_noise1, B = B1 = lin1_w, C = g_mlph
__global__ void sgemm128_kernel(int tag, const float* __restrict__ Aparam,
                                const float* __restrict__ B1,
                                const float* __restrict__ B2,
                                const float* __restrict__ bias, int act) {
    const int M = NN, N = 128, K = 128;
    const int BK = 16;
    __shared__ float As[BK][128 + 4];   // +4 keeps rows 16B-aligned for float4 reads
    __shared__ float Bs[BK][128];
    const float* A = (tag == 2) ? (const float*)g_noise1 : Aparam;
    const float* B = (tag == 0 && blockIdx.y == 1) ? B2 : B1;
    float* C = (tag == 2) ? g_mlph : (blockIdx.y == 0 ? g_xl1 : g_xr1);

    int row0 = blockIdx.x * 128;
    int tid = threadIdx.x;                 // 256
    int tx = tid % 16, ty = tid / 16;      // 16x16 threads, each 8x8 outputs
    int lr = tid / 16, lc = tid % 16;      // A load: row lr+16i, k-col lc
    int bc = tid % 128, br0 = tid / 128;   // B load: rows br0+2i, col bc
    float acc[8][8] = {};
    for (int k0 = 0; k0 < K; k0 += BK) {
#pragma unroll
        for (int i = 0; i < 8; i++) {
            int r = row0 + lr + 16 * i;
            float v = 0.f;
            if (r < M) v = A[(size_t)r * K + k0 + lc];
            As[lc][lr + 16 * i] = v;
        }
#pragma unroll
        for (int i = 0; i < 8; i++) {
            int kr = k0 + br0 + 2 * i;
            Bs[br0 + 2 * i][bc] = B[(size_t)kr * N + bc];
        }
        __syncthreads();
#pragma unroll
        for (int kk = 0; kk < BK; kk++) {
            float a[8], b[8];
            float4 a0 = *(const float4*)&As[kk][ty * 8];
            float4 a1 = *(const float4*)&As[kk][ty * 8 + 4];
            a[0]=a0.x; a[1]=a0.y; a[2]=a0.z; a[3]=a0.w;
            a[4]=a1.x; a[5]=a1.y; a[6]=a1.z; a[7]=a1.w;
            float4 b0 = *(const float4*)&Bs[kk][tx * 8];
            float4 b1 = *(const float4*)&Bs[kk][tx * 8 + 4];
            b[0]=b0.x; b[1]=b0.y; b[2]=b0.z; b[3]=b0.w;
            b[4]=b1.x; b[5]=b1.y; b[6]=b1.z; b[7]=b1.w;
#pragma unroll
            for (int i = 0; i < 8; i++)
#pragma unroll
                for (int j = 0; j < 8; j++) acc[i][j] += a[i] * b[j];
        }
        __syncthreads();
    }
#pragma unroll
    for (int i = 0; i < 8; i++) {
        int r = row0 + ty * 8 + i;
        if (r >= M) continue;
#pragma unroll
        for (int j = 0; j < 8; j++) {
            int c = tx * 8 + j;
            float v = acc[i][j];
            if (bias) v += bias[c];
            if (act == 1) v = (v > 0.f) ? v : expm1f(v);
            C[(size_t)r * N + c] = v;
        }
    }
}

// N=16 GEMM: g_n1[M,16] = g_mlph[M,128] @ B[128,16] + bias
__global__ void sgemm_n16_kernel(const float* __restrict__ B,
                                 const float* __restrict__ bias) {
    const int M = NN, K = 128;
    __shared__ float Bs[K * 16];
    __shared__ float As[16][K];
    int tid = threadIdx.x;              // 256
    int tx = tid % 16, ty = tid / 16;
    for (int i = tid; i < K * 16; i += 256) Bs[i] = B[i];
    int r = blockIdx.x * 16 + ty;
#pragma unroll
    for (int i = 0; i < 8; i++) {
        int c = tx + 16 * i;
        As[ty][c] = (r < M) ? g_mlph[(size_t)r * K + c] : 0.f;
    }
    __syncthreads();
    float acc = 0.f;
#pragma unroll 8
    for (int k = 0; k < K; k++) acc += As[ty][k] * Bs[k * 16 + tx];
    if (r < M) g_n1[(size_t)r * 16 + tx] = acc + bias[tx];
}

// dual N=16 GEMM: xl2 = h1 @ Wl2, xr2 = h1 @ Wr2 (A read once)
__global__ void sgemm_n16_dual_kernel(const float* __restrict__ Bl,
                                      const float* __restrict__ Br) {
    const int M = NN, K = 128;
    __shared__ float Bsl[K * 16];
    __shared__ float Bsr[K * 16];
    __shared__ float As[16][K];
    int tid = threadIdx.x;
    int tx = tid % 16, ty = tid / 16;
    for (int i = tid; i < K * 16; i += 256) { Bsl[i] = Bl[i]; Bsr[i] = Br[i]; }
    int r = blockIdx.x * 16 + ty;
#pragma unroll
    for (int i = 0; i < 8; i++) {
        int c = tx + 16 * i;
        As[ty][c] = (r < M) ? g_h1[(size_t)r * K + c] : 0.f;
    }
    __syncthreads();
    float accl = 0.f, accr = 0.f;
#pragma unroll 8
    for (int k = 0; k < K; k++) {
        float a = As[ty][k];
        accl += a * Bsl[k * 16 + tx];
        accr += a * Bsr[k * 16 + tx];
    }
    if (r < M) {
        g_xl2[(size_t)r * 16 + tx] = accl;
        g_xr2[(size_t)r * 16 + tx] = accr;
    }
}

// ---------------- edge scores layer 1: warp per CSR position ----------------------
// CSR order => consecutive warps share the same dst row (L1 reuse for xr).
__global__ void edge_scores1_kernel(const float* __restrict__ att) {
    int w = blockIdx.x * (blockDim.x >> 5) + (threadIdx.x >> 5);
    if (w >= NE) return;
    int lane = threadIdx.x & 31;
    int s = g_srcc[w], d = g_dstc[w];
    float4 a = *(const float4*)(g_xl1 + (size_t)s * D1 + lane * 4);
    float4 b = *(const float4*)(g_xr1 + (size_t)d * D1 + lane * 4);
    float4 t = __ldg((const float4*)att + lane);
    float vx = a.x + b.x; vx = (vx > 0.f) ? vx : NEG_SLOPE * vx;
    float vy = a.y + b.y; vy = (vy > 0.f) ? vy : NEG_SLOPE * vy;
    float vz = a.z + b.z; vz = (vz > 0.f) ? vz : NEG_SLOPE * vz;
    float vw = a.w + b.w; vw = (vw > 0.f) ? vw : NEG_SLOPE * vw;
    float p = vx * t.x + vy * t.y + vz * t.z + vw * t.w;
    p += __shfl_xor_sync(0xffffffffu, p, 1);
    p += __shfl_xor_sync(0xffffffffu, p, 2);
    p += __shfl_xor_sync(0xffffffffu, p, 4);
    if ((lane & 7) == 0) g_scores1[(size_t)w * HEADS + (lane >> 3)] = p;
}

// ---------------- edge scores layer 2: warp handles 8 CSR positions ---------------
__global__ void edge_scores2_kernel(const float* __restrict__ att) {
    int w = blockIdx.x * (blockDim.x >> 5) + (threadIdx.x >> 5);
    int lane = threadIdx.x & 31;
    int sub = lane >> 2;          // 0..7 position within warp
    int i = lane & 3;             // float4 chunk
    int e = w * 8 + sub;
    float p = 0.f;
    if (e < NE) {
        int s = g_srcc[e], d = g_dstc[e];
        float4 a = *(const float4*)(g_xl2 + (size_t)s * NCLS + i * 4);
        float4 b = *(const float4*)(g_xr2 + (size_t)d * NCLS + i * 4);
        float4 t = __ldg((const float4*)att + i);
        float vx = a.x + b.x; vx = (vx > 0.f) ? vx : NEG_SLOPE * vx;
        float vy = a.y + b.y; vy = (vy > 0.f) ? vy : NEG_SLOPE * vy;
        float vz = a.z + b.z; vz = (vz > 0.f) ? vz : NEG_SLOPE * vz;
        float vw = a.w + b.w; vw = (vw > 0.f) ? vw : NEG_SLOPE * vw;
        p = vx * t.x + vy * t.y + vz * t.z + vw * t.w;
    }
    p += __shfl_xor_sync(0xffffffffu, p, 1);
    p += __shfl_xor_sync(0xffffffffu, p, 2);
    if (i == 0 && e < NE) g_scores2[e] = p;
}

// ---------------- top-k + dual masked softmax: 2 passes ---------------------------
// Pass 1: top-k insertion; rejected/evicted items feed an online softmax
//         (noise max + sum). sumk computed from the register-resident list.
// Pass 2: write alpha / alphan.
__global__ void topk_alpha_kernel(int layer, const int* __restrict__ kptr) {
    const int H = (layer == 1) ? HEADS : 1;
    const float* scores = (layer == 1) ? (const float*)g_scores1 : (const float*)g_scores2;
    float* alpha  = (layer == 1) ? g_alpha1  : g_alpha2;
    float* alphan = (layer == 1) ? g_alphan1 : g_alphan2;

    int t = blockIdx.x * blockDim.x + threadIdx.x;
    if (t >= NN * H) return;
    int n = t / H, h = t - n * H;
    int beg = g_offs[n], cnt = g_counts[n];
    if (cnt == 0) return;
    int k = *kptr;
    if (k > KMAX) k = KMAX;
    if (k < 0) k = 0;

    float ts[KMAX];
    int   te[KMAX];
    int m = 0;
    float mn = -__int_as_float(0x7f800000);  // online noise max
    float sn = 0.f;                          // online noise sum (ref mn)
    for (int p = 0; p < cnt; p++) {
        int idx = beg + p;
        float s = scores[(size_t)idx * H + h];
        int e = g_eid[idx];
        float rej_s;
        bool have_rej = false;
        if (m < k) {
            int i = m++;
            while (i > 0 && (s > ts[i - 1] || (s == ts[i - 1] && e < te[i - 1]))) {
                ts[i] = ts[i - 1]; te[i] = te[i - 1]; i--;
            }
            ts[i] = s; te[i] = e;
        } else if (k > 0 && (s > ts[k - 1] || (s == ts[k - 1] && e < te[k - 1]))) {
            rej_s = ts[k - 1];               // evicted
            have_rej = true;
            int i = k - 1;
            while (i > 0 && (s > ts[i - 1] || (s == ts[i - 1] && e < te[i - 1]))) {
                ts[i] = ts[i - 1]; te[i] = te[i - 1]; i--;
            }
            ts[i] = s; te[i] = e;
        } else {
            rej_s = s;                       // rejected (also handles k == 0)
            have_rej = true;
        }
        if (have_rej) {
            if (rej_s <= mn) sn += expf(rej_s - mn);
            else { sn = sn * expf(mn - rej_s) + 1.f; mn = rej_s; }
        }
    }
    bool all_kept = (cnt <= k);
    float thr_s = (m > 0) ? ts[m - 1] : __int_as_float(0x7f800000);
    int   thr_e = (m > 0) ? te[m - 1] : -1;
    float mk = (m > 0) ? ts[0] : 0.f;

    float sumk = 0.f;
    for (int i = 0; i < m; i++) sumk += expf(ts[i] - mk);

    if (!isfinite(mn)) mn = 0.f;            // no noise edges
    float invk = 1.f / (sumk + 1e-16f);
    float invn = 1.f / (sn + 1e-16f);

    for (int p = 0; p < cnt; p++) {
        int idx = beg + p;
        float s = scores[(size_t)idx * H + h];
        int e = g_eid[idx];
        bool kept = all_kept || (s > thr_s) || (s == thr_s && e <= thr_e);
        size_t o = (size_t)idx * H + h;
        if (kept) { alpha[o] = expf(s - mk) * invk; alphan[o] = 0.f; }
        else      { alpha[o] = 0.f;                 alphan[o] = expf(s - mn) * invn; }
    }
}

// ---------------- aggregation layer 1: warp per (node, head), lane = channel -------
__global__ void aggregate1_kernel(const float* __restrict__ b1) {
    int w = blockIdx.x * (blockDim.x >> 5) + (threadIdx.x >> 5);
    if (w >= NN * HEADS) return;
    int lane = threadIdx.x & 31;
    int n = w >> 2, h = w & 3;
    int beg = g_offs[n], cnt = g_counts[n];
    float acc = 0.f, accn = 0.f;
    for (int p = 0; p < cnt; p++) {
        int idx = beg + p;
        float a  = g_alpha1[(size_t)idx * HEADS + h];
        float an = g_alphan1[(size_t)idx * HEADS + h];
        int s = g_srcc[idx];
        float xv = g_xl1[(size_t)s * D1 + h * 32 + lane];
        acc  += a * xv;
        accn += an * xv;
    }
    int c = h * 32 + lane;
    float bb = b1[c];
    float o = acc + bb;
    g_h1[(size_t)n * D1 + c]     = (o > 0.f) ? o : expm1f(o);
    g_noise1[(size_t)n * D1 + c] = accn + bb;
}

// ---------------- aggregation layer 2: half-warp per node, lane = class ------------
__global__ void aggregate2_kernel(const float* __restrict__ b2) {
    int w = blockIdx.x * (blockDim.x >> 5) + (threadIdx.x >> 5);
    int lane = threadIdx.x & 31;
    int sub = lane >> 4;
    int c = lane & 15;
    int n = w * 2 + sub;
    if (n >= NN) return;
    int beg = g_offs[n], cnt = g_counts[n];
    float acc = 0.f, accn = 0.f;
    for (int p = 0; p < cnt; p++) {
        int idx = beg + p;
        float a  = g_alpha2[idx];
        float an = g_alphan2[idx];
        int s = g_srcc[idx];
        float xv = g_xl2[(size_t)s * NCLS + c];
        acc  += a * xv;
        accn += an * xv;
    }
    float bb = b2[c];
    g_out2[(size_t)n * NCLS + c]   = acc + bb;
    g_noise2[(size_t)n * NCLS + c] = accn + bb;
}

// ---------------- log_softmax over 16 classes, thread per row, 3 inputs ------------
__global__ void log_softmax16_kernel(float* __restrict__ out) {
    int r = blockIdx.x * blockDim.x + threadIdx.x;
    if (r >= 3 * NN) return;
    const float* in = (r < NN) ? (const float*)g_out2
                    : (r < 2 * NN) ? (const float*)g_n1 - (size_t)NN * NCLS
                    : (const float*)g_noise2 - 2 * (size_t)NN * NCLS;
    float v[NCLS];
    float mx = -3.4e38f;
#pragma unroll
    for (int c = 0; c < NCLS; c++) { v[c] = in[(size_t)r * NCLS + c]; mx = fmaxf(mx, v[c]); }
    float s = 0.f;
#pragma unroll
    for (int c = 0; c < NCLS; c++) s += expf(v[c] - mx);
    float ls = mx + logf(s);
#pragma unroll
    for (int c = 0; c < NCLS; c++) out[(size_t)r * NCLS + c] = v[c] - ls;
}

// ---------------- host ----------------
extern "C" void kernel_launch(void* const* d_in, const int* in_sizes, int n_in,
                              void* d_out, int out_size) {
    const float* x      = (const float*)d_in[0];
    const int*   ei     = (const int*)d_in[1];
    const int*   kptr   = (const int*)d_in[2];
    const float* Wl1    = (const float*)d_in[3];
    const float* Wr1    = (const float*)d_in[4];
    const float* att1   = (const float*)d_in[5];
    const float* b1     = (const float*)d_in[6];
    const float* Wl2    = (const float*)d_in[7];
    const float* Wr2    = (const float*)d_in[8];
    const float* att2   = (const float*)d_in[9];
    const float* b2     = (const float*)d_in[10];
    const float* lin1_w = (const float*)d_in[11];
    const float* lin1_b = (const float*)d_in[12];
    const float* lin2_w = (const float*)d_in[13];
    const float* lin2_b = (const float*)d_in[14];
    float* out = (float*)d_out;

    // --- CSR build ---
    init_csr_kernel<<<(NN + 255) / 256, 256>>>();
    convert_count_kernel<<<(NE + 255) / 256, 256>>>(ei);
    block_sum_kernel<<<NBLK_SCAN, 256>>>();
    scan_partials_kernel<<<1, 256>>>();
    scan_final_kernel<<<NBLK_SCAN, 256>>>();
    scatter_kernel<<<(NE + 255) / 256, 256>>>();

    // --- layer 1 projections (fused xl1+xr1) ---
    dim3 gProj((NN + 127) / 128, 2);
    sgemm128_kernel<<<gProj, 256>>>(0, x, Wl1, Wr1, nullptr, 0);

    // --- layer 1 attention ---
    edge_scores1_kernel<<<(NE + 7) / 8, 256>>>(att1);
    topk_alpha_kernel<<<(NN * HEADS + 255) / 256, 256>>>(1, kptr);
    aggregate1_kernel<<<(NN * HEADS + 7) / 8, 256>>>(b1);

    // --- noise MLP ---
    dim3 gMlp((NN + 127) / 128, 1);
    sgemm128_kernel<<<gMlp, 256>>>(2, nullptr, lin1_w, nullptr, lin1_b, 1);
    sgemm_n16_kernel<<<(NN + 15) / 16, 256>>>(lin2_w, lin2_b);

    // --- layer 2 projections (fused xl2+xr2) ---
    sgemm_n16_dual_kernel<<<(NN + 15) / 16, 256>>>(Wl2, Wr2);

    // --- layer 2 attention ---
    edge_scores2_kernel<<<((NE + 7) / 8 + 7) / 8, 256>>>(att2);
    topk_alpha_kernel<<<(NN + 255) / 256, 256>>>(2, kptr);
    aggregate2_kernel<<<((NN + 1) / 2 + 7) / 8, 256>>>(b2);

    // --- outputs (single fused log_softmax over 3*NN rows) ---
    log_softmax16_kernel<<<(3 * NN + 255) / 256, 256>>>(out);
}